// round 5
// baseline (speedup 1.0000x reference)
#include <cuda_runtime.h>

// Fixed problem shape (PANUMPooling_8787503088315)
#define NB   8        // graphs
#define NPG  2048     // nodes per graph
#define KP   1024     // kept per graph
#define FD   128      // feature dim
#define NTOT (NB * NPG)   // 16384 total nodes
#define NK   (NB * KP)    // 8192 kept nodes

// Scratch (device globals: no allocation allowed)
__device__ int   g_perm[NK];
__device__ float g_score[NK];
__device__ int   g_nodemap[NTOT];

static __device__ __forceinline__ unsigned um32(unsigned a, unsigned b) { return a > b ? a : b; }
static __device__ __forceinline__ unsigned un32(unsigned a, unsigned b) { return a < b ? a : b; }

// ---------------------------------------------------------------------------
// Kernel 1: per-graph score + stable top-K.
// Register bitonic sort of BARE u32 monotone-float keys (thread t owns
// elements 2t, 2t+1), then each ORIGINAL element binary-searches the sorted
// key array for its rank; winners (rank < K) emit outputs directly (they
// still hold their original index + diag value in registers).
// Ties (equal fp32 diag values): detected via sA[p+1]==x; resolved by
// scanning the original-key array counting equal keys with smaller index
// (exactly stable argsort(-score)). Rare path, exact.
//   j==1          : intra-thread compare            (no smem, no sync)
//   j in [2,32]   : shfl.xor, 1 SHFL + IMNMX        (no smem, no sync)
//   j in [64,1024]: ping-pong SMEM (uint2), 1 __syncthreads per stage
// ---------------------------------------------------------------------------
__global__ __launch_bounds__(1024, 1)
void topk_kernel(const float* __restrict__ UM, float* __restrict__ out,
                 int offBatch, int offPerm, int offScore)
{
    __shared__ unsigned okeys[NPG];   // original keys by index (for tie scan)
    __shared__ unsigned sA[NPG];      // ping-pong / final sorted keys
    __shared__ unsigned sB[NPG];

    const int g    = blockIdx.x;
    const int tid  = threadIdx.x;
    const int base = g * NPG;
    const int e0   = 2 * tid;

    // Prologue: load 2 diag entries, build monotone keys, record originals,
    // init node_map for owned slots.
    float d0, d1;
    unsigned k0, k1, m0, m1;
    {
        const int n0 = base + e0;
        const int n1 = n0 + 1;
        d0 = UM[(size_t)n0 * NTOT + n0];
        d1 = UM[(size_t)n1 * NTOT + n1];
        const unsigned b0 = __float_as_uint(d0);
        const unsigned b1 = __float_as_uint(d1);
        m0 = (b0 & 0x80000000u) ? ~b0 : (b0 | 0x80000000u);
        m1 = (b1 & 0x80000000u) ? ~b1 : (b1 | 0x80000000u);
        k0 = m0; k1 = m1;
        okeys[e0]     = m0;
        okeys[e0 + 1] = m1;
        g_nodemap[n0] = -1;
        g_nodemap[n1] = -1;
    }

    // Bitonic sort, descending, keys only.
    bool useA = true;
    for (int k = 2; k <= NPG; k <<= 1) {
        const bool bigFirst = ((e0 & k) == 0);

        // cross-warp stages: j >= 64 (thread-offset >= 32)
        for (int j = k >> 1; j >= 64; j >>= 1) {
            unsigned* wb = useA ? sA : sB;
            ((uint2*)wb)[tid] = make_uint2(k0, k1);
            __syncthreads();
            const uint2 r = ((const uint2*)wb)[tid ^ (j >> 1)];
            const bool keepMax = (((tid & (j >> 1)) == 0) == bigFirst);
            k0 = keepMax ? um32(k0, r.x) : un32(k0, r.x);
            k1 = keepMax ? um32(k1, r.y) : un32(k1, r.y);
            useA = !useA;
        }

        // warp-local shfl stages: j in [2, 32]
        for (int j = (k >> 1 < 32 ? k >> 1 : 32); j >= 2; j >>= 1) {
            const int half = j >> 1;
            const unsigned r0 = __shfl_xor_sync(0xFFFFFFFFu, k0, half);
            const unsigned r1 = __shfl_xor_sync(0xFFFFFFFFu, k1, half);
            const bool keepMax = (((tid & half) == 0) == bigFirst);
            k0 = keepMax ? um32(k0, r0) : un32(k0, r0);
            k1 = keepMax ? um32(k1, r1) : un32(k1, r1);
        }

        // j == 1: intra-thread
        {
            const bool bf1 = ((e0 & k) == 0);
            if (bf1 ? (k0 < k1) : (k0 > k1)) { unsigned t = k0; k0 = k1; k1 = t; }
        }
    }

    // Publish sorted keys (barrier first: last SMEM-stage reads must drain).
    __syncthreads();
    ((uint2*)sA)[tid] = make_uint2(k0, k1);
    __syncthreads();

    const unsigned thr = sA[KP - 1];   // K-th largest key (broadcast)

    // Each original element finds its rank; winners emit.
    #pragma unroll
    for (int s = 0; s < 2; s++) {
        const unsigned x = s ? m1 : m0;
        const float   dv = s ? d1 : d0;
        if (x < thr) continue;                    // rank >= KP for sure, skip
        // count of sorted keys strictly greater than x (descending array)
        int p = 0;
        #pragma unroll
        for (int step = NPG / 2; step > 0; step >>= 1)
            if (sA[p + step - 1] > x) p += step;
        int rank = p;
        if (p + 1 < NPG && sA[p + 1] == x) {      // rare: duplicate key
            const int iloc = e0 + s;
            int off = 0;
            #pragma unroll 1
            for (int j = 0; j < iloc; j++) off += (okeys[j] == x);
            rank = p + off;
        }
        if (rank < KP) {
            const int node = base + e0 + s;
            const float sc = tanhf(dv);
            const int row  = g * KP + rank;
            g_perm[row]     = node;
            g_score[row]    = sc;
            g_nodemap[node] = row;
            out[offBatch + row] = (float)g;
            out[offPerm  + row] = (float)node;
            out[offScore + row] = sc;
        }
    }
}

// ---------------------------------------------------------------------------
// Kernel 2: x_new[row] = x[perm[row]] * score[row]   (one warp per row, float4)
// ---------------------------------------------------------------------------
__global__ __launch_bounds__(256)
void gather_kernel(const float* __restrict__ x, float* __restrict__ out)
{
    const int row  = blockIdx.x * 8 + (threadIdx.x >> 5);
    const int lane = threadIdx.x & 31;
    const int src  = g_perm[row];
    const float sc = g_score[row];
    float4 v = ((const float4*)x)[(size_t)src * (FD / 4) + lane];
    v.x *= sc; v.y *= sc; v.z *= sc; v.w *= sc;
    ((float4*)out)[(size_t)row * (FD / 4) + lane] = v;
}

// ---------------------------------------------------------------------------
// Kernel 3: edge remap, 4 edges per thread (vectorized loads/stores).
// ---------------------------------------------------------------------------
__global__ __launch_bounds__(256)
void edge_kernel(const int* __restrict__ ei, const float* __restrict__ ew,
                 float* __restrict__ out, int E, int offEI, int offEW)
{
    const int e4 = blockIdx.x * blockDim.x + threadIdx.x;
    if (e4 >= E / 4) return;

    const int4   rsrc = ((const int4*)ei)[e4];
    const int4   csrc = ((const int4*)(ei + E))[e4];
    const float4 w    = ((const float4*)ew)[e4];

    int   r[4] = { g_nodemap[rsrc.x], g_nodemap[rsrc.y], g_nodemap[rsrc.z], g_nodemap[rsrc.w] };
    int   c[4] = { g_nodemap[csrc.x], g_nodemap[csrc.y], g_nodemap[csrc.z], g_nodemap[csrc.w] };
    float wv[4] = { w.x, w.y, w.z, w.w };

    float ro[4], co[4], wo[4];
    #pragma unroll
    for (int s = 0; s < 4; s++) {
        const bool ok = (r[s] >= 0) & (c[s] >= 0);
        ro[s] = ok ? (float)r[s] : -1.0f;
        co[s] = ok ? (float)c[s] : -1.0f;
        wo[s] = ok ? wv[s] : 0.0f;
    }
    ((float4*)(out + offEI))[e4]     = make_float4(ro[0], ro[1], ro[2], ro[3]);
    ((float4*)(out + offEI + E))[e4] = make_float4(co[0], co[1], co[2], co[3]);
    ((float4*)(out + offEW))[e4]     = make_float4(wo[0], wo[1], wo[2], wo[3]);
}

// ---------------------------------------------------------------------------
// Launch. Inputs (metadata order): x[N,F] f32, UM[N,N] f32, edge_index[2,E] i32,
// edge_weight[E] f32, batch[N] i32.
// ---------------------------------------------------------------------------
extern "C" void kernel_launch(void* const* d_in, const int* in_sizes, int n_in,
                              void* d_out, int out_size)
{
    const float* x  = (const float*)d_in[0];
    const float* UM = (const float*)d_in[1];
    const int*   ei = (const int*)d_in[2];
    const float* ew = (const float*)d_in[3];
    float* out = (float*)d_out;

    const int E = in_sizes[3];

    const int offX     = 0;
    const int offEI    = offX  + NK * FD;      // 1048576
    const int offEW    = offEI + 2 * E;        // 1572864
    const int offBatch = offEW + E;            // 1835008
    const int offPerm  = offBatch + NK;        // 1843200
    const int offScore = offPerm + NK;         // 1851392

    topk_kernel<<<NB, 1024>>>(UM, out, offBatch, offPerm, offScore);
    gather_kernel<<<NK / 8, 256>>>(x, out + offX);
    edge_kernel<<<(E / 4 + 255) / 256, 256>>>(ei, ew, out, E, offEI, offEW);
}